// round 1
// baseline (speedup 1.0000x reference)
#include <cuda_runtime.h>
#include <math.h>

#define LDIM 512
#define BDIM 64
#define CDIM 512

// Scratch (no dynamic allocation allowed)
__device__ __align__(16) float g_E[CDIM * CDIM];   // exp(trans)
__device__ float g_logz[BDIM];                     // per-batch log partition
__device__ float g_scorep[BDIM];                   // per-block score partials
__device__ int   g_mask_byte;                      // 1 if mask stored as 1-byte bools

// ---------------------------------------------------------------------------
// Probe mask dtype: row 0 of mask (mask[0, b]) is guaranteed all-true
// (lens >= L/2). If the buffer holds int32 ones, the byte view of the first
// 64 entries is 1,0,0,0,1,0,0,0,... -> not all nonzero. If uint8 bools,
// all 64 bytes are nonzero.
__global__ void probe_mask_kernel(const unsigned char* __restrict__ m8) {
    int allnz = 1;
    for (int b = 0; b < BDIM; b++)
        if (m8[b] == 0) allnz = 0;
    g_mask_byte = allnz;
}

__device__ __forceinline__ int get_mask(const void* mask, int idx) {
    if (g_mask_byte)
        return ((const unsigned char*)mask)[idx] != 0;
    return ((const int*)mask)[idx] != 0;
}

// ---------------------------------------------------------------------------
// E[c][c'] = exp(trans[c][c'])  (one-time; trans is step/batch invariant)
__global__ void exp_trans_kernel(const float* __restrict__ trans) {
    int i = blockIdx.x * blockDim.x + threadIdx.x;
    g_E[i] = expf(trans[i]);
}

// ---------------------------------------------------------------------------
// Forward recursion: one CTA per batch element, 512 threads (thread t owns
// state c' = t). alpha in registers, p = exp(alpha - m) in SMEM,
// E streamed from L2 with float4 loads (thread (seg,u) covers reduction rows
// [128*seg, 128*seg+128) x output cols [4u, 4u+4)).
__global__ __launch_bounds__(512) void forward_kernel(
    const float* __restrict__ emit,
    const void*  __restrict__ mask,
    const float* __restrict__ tfs,
    const float* __restrict__ tte)
{
    const int b    = blockIdx.x;
    const int t    = threadIdx.x;
    const int warp = t >> 5, lane = t & 31;
    const int seg  = t >> 7, u    = t & 127;

    __shared__ float  p[CDIM];
    __shared__ float4 part[4][128];   // part[seg][u] = partial sums for cols 4u..4u+3
    __shared__ float  red[17];

    // log_alpha0 = emit[0, b, :] + trans_from_start
    float a = emit[(size_t)b * CDIM + t] + tfs[t];

    const float4* E4 = (const float4*)g_E;

    for (int i = 1; i < LDIM; i++) {
        if (!get_mask(mask, i * BDIM + b)) continue;   // uniform across block

        // ---- block max of alpha (numerical stabilizer) ----
        float m = a;
        #pragma unroll
        for (int o = 16; o; o >>= 1) m = fmaxf(m, __shfl_xor_sync(0xffffffffu, m, o));
        if (lane == 0) red[warp] = m;
        __syncthreads();
        if (warp == 0) {
            float v = (lane < 16) ? red[lane] : -3.4e38f;
            #pragma unroll
            for (int o = 8; o; o >>= 1) v = fmaxf(v, __shfl_xor_sync(0xffffffffu, v, o));
            if (lane == 0) red[16] = v;
        }
        __syncthreads();
        m = red[16];

        // ---- p = exp(alpha - m) ----
        p[t] = expf(a - m);
        __syncthreads();

        // ---- matvec: s[c'] = sum_c p[c] * E[c][c'] ----
        float4 acc = make_float4(0.f, 0.f, 0.f, 0.f);
        const float4* Eb = E4 + (size_t)seg * (128 * 128) + u;
        const float*  ps = &p[seg * 128];
        #pragma unroll 8
        for (int c = 0; c < 128; c++) {
            float  pv = ps[c];                 // SMEM broadcast
            float4 e  = Eb[(size_t)c * 128];   // coalesced 512B/warp
            acc.x = fmaf(pv, e.x, acc.x);
            acc.y = fmaf(pv, e.y, acc.y);
            acc.z = fmaf(pv, e.z, acc.z);
            acc.w = fmaf(pv, e.w, acc.w);
        }
        part[seg][u] = acc;
        __syncthreads();

        // ---- combine 4 segments, update alpha ----
        const float* pf = (const float*)part;
        float s = (pf[t] + pf[512 + t]) + (pf[1024 + t] + pf[1536 + t]);
        a = m + logf(s) + emit[((size_t)i * BDIM + b) * CDIM + t];
        // (no trailing barrier needed: next iteration's SMEM writes are all
        //  fenced behind its own two reduction barriers)
    }

    // ---- log_z_b = logsumexp(alpha + trans_to_end) ----
    float v = a + tte[t];
    float m = v;
    #pragma unroll
    for (int o = 16; o; o >>= 1) m = fmaxf(m, __shfl_xor_sync(0xffffffffu, m, o));
    if (lane == 0) red[warp] = m;
    __syncthreads();
    if (warp == 0) {
        float w = (lane < 16) ? red[lane] : -3.4e38f;
        #pragma unroll
        for (int o = 8; o; o >>= 1) w = fmaxf(w, __shfl_xor_sync(0xffffffffu, w, o));
        if (lane == 0) red[16] = w;
    }
    __syncthreads();
    m = red[16];

    float e = expf(v - m);
    #pragma unroll
    for (int o = 16; o; o >>= 1) e += __shfl_xor_sync(0xffffffffu, e, o);
    __syncthreads();                 // red reuse fence
    if (lane == 0) red[warp] = e;
    __syncthreads();
    if (t == 0) {
        float tot = 0.f;
        #pragma unroll
        for (int w2 = 0; w2 < 16; w2++) tot += red[w2];   // fixed order: deterministic
        g_logz[b] = m + logf(tot);
    }
}

// ---------------------------------------------------------------------------
// Score: fully parallel over (i, b). Contribution of position (i,b), if masked:
//   emit[i,b,target[i,b]] (+ trans[target[i-1,b], target[i,b]] if i>0)
//   (+ tfs[target[0,b]] if i==0)  (+ tte[target[i,b]] if last active i)
__global__ __launch_bounds__(512) void score_kernel(
    const float* __restrict__ emit,
    const int*   __restrict__ target,
    const void*  __restrict__ mask,
    const float* __restrict__ trans,
    const float* __restrict__ tfs,
    const float* __restrict__ tte)
{
    const int idx = blockIdx.x * 512 + threadIdx.x;   // 64 blocks x 512 = L*B
    const int i = idx >> 6;
    const int b = idx & 63;
    const int t = threadIdx.x, warp = t >> 5, lane = t & 31;

    float contrib = 0.f;
    if (get_mask(mask, i * BDIM + b)) {
        int ti = target[i * BDIM + b];
        contrib = emit[((size_t)i * BDIM + b) * CDIM + ti];
        if (i > 0) {
            int tp = target[(i - 1) * BDIM + b];
            contrib += trans[(size_t)tp * CDIM + ti];
        } else {
            contrib += tfs[ti];
        }
        int nxt = (i + 1 < LDIM) ? get_mask(mask, (i + 1) * BDIM + b) : 0;
        if (!nxt) contrib += tte[ti];   // mask is a prefix: this is the last step
    }

    // deterministic block sum
    __shared__ float red[16];
    #pragma unroll
    for (int o = 16; o; o >>= 1) contrib += __shfl_xor_sync(0xffffffffu, contrib, o);
    if (lane == 0) red[warp] = contrib;
    __syncthreads();
    if (t == 0) {
        float s = 0.f;
        #pragma unroll
        for (int w = 0; w < 16; w++) s += red[w];
        g_scorep[blockIdx.x] = s;
    }
}

// ---------------------------------------------------------------------------
__global__ void finalize_kernel(float* __restrict__ out) {
    if (threadIdx.x == 0) {
        float lz = 0.f, sc = 0.f;
        for (int b = 0; b < BDIM; b++) { lz += g_logz[b]; sc += g_scorep[b]; }
        out[0] = (lz - sc) / (float)BDIM;
    }
}

// ---------------------------------------------------------------------------
extern "C" void kernel_launch(void* const* d_in, const int* in_sizes, int n_in,
                              void* d_out, int out_size) {
    // metadata order: emit, target, mask, trans, trans_from_start, trans_to_end
    const float* emit   = (const float*)d_in[0];
    const int*   target = (const int*)  d_in[1];
    const void*  mask   =               d_in[2];
    const float* trans  = (const float*)d_in[3];
    const float* tfs    = (const float*)d_in[4];
    const float* tte    = (const float*)d_in[5];
    float* out = (float*)d_out;

    probe_mask_kernel<<<1, 1>>>((const unsigned char*)mask);
    exp_trans_kernel<<<(CDIM * CDIM) / 512, 512>>>(trans);
    forward_kernel<<<BDIM, 512>>>(emit, mask, tfs, tte);
    score_kernel<<<64, 512>>>(emit, target, mask, trans, tfs, tte);
    finalize_kernel<<<1, 32>>>(out);
}

// round 2
// speedup vs baseline: 1.5830x; 1.5830x over previous
#include <cuda_runtime.h>
#include <math.h>
#include <stdint.h>

#define LDIM 512
#define BDIM 64
#define CDIM 512
#define RANKS 4
#define COLS 128          // E-columns per CTA (CDIM / RANKS)

// Scratch (no dynamic allocation allowed)
__device__ __align__(16) float g_E[CDIM * CDIM];   // exp(trans)
__device__ float g_logz[BDIM];
__device__ float g_scorep[BDIM];
__device__ int   g_mask_byte;

// ---------------------------------------------------------------------------
// helpers
__device__ __forceinline__ unsigned smem_u32(const void* p) {
    return (unsigned)__cvta_generic_to_shared(p);
}
__device__ __forceinline__ unsigned mapa_rank(unsigned saddr, unsigned rank) {
    unsigned r;
    asm("mapa.shared::cluster.u32 %0, %1, %2;" : "=r"(r) : "r"(saddr), "r"(rank));
    return r;
}
__device__ __forceinline__ void stc_f32(unsigned saddr, float v) {
    asm volatile("st.shared::cluster.f32 [%0], %1;" :: "r"(saddr), "f"(v) : "memory");
}
__device__ __forceinline__ void cluster_sync_() {
    asm volatile("barrier.cluster.arrive.aligned;" ::: "memory");
    asm volatile("barrier.cluster.wait.aligned;"   ::: "memory");
}
// packed f32x2 fma:  d = a*b + c  (elementwise on 2 packed floats)
__device__ __forceinline__ unsigned long long ffma2(unsigned long long a,
                                                    unsigned long long b,
                                                    unsigned long long c) {
    unsigned long long d;
    asm("fma.rn.f32x2 %0, %1, %2, %3;" : "=l"(d) : "l"(a), "l"(b), "l"(c));
    return d;
}
__device__ __forceinline__ unsigned long long dup2(float v) {
    unsigned long long r; unsigned u = __float_as_uint(v);
    asm("mov.b64 %0, {%1, %1};" : "=l"(r) : "r"(u));
    return r;
}
__device__ __forceinline__ void unpack2(unsigned long long v, float& x, float& y) {
    unsigned a, b;
    asm("mov.b64 {%0, %1}, %2;" : "=r"(a), "=r"(b) : "l"(v));
    x = __uint_as_float(a); y = __uint_as_float(b);
}

// ---------------------------------------------------------------------------
__global__ void probe_mask_kernel(const unsigned char* __restrict__ m8) {
    int allnz = 1;
    for (int b = 0; b < BDIM; b++)
        if (m8[b] == 0) allnz = 0;
    g_mask_byte = allnz;
}
__device__ __forceinline__ int get_mask(const void* mask, int idx) {
    if (g_mask_byte) return ((const unsigned char*)mask)[idx] != 0;
    return ((const int*)mask)[idx] != 0;
}

__global__ void exp_trans_kernel(const float* __restrict__ trans) {
    int i = blockIdx.x * blockDim.x + threadIdx.x;
    g_E[i] = expf(trans[i]);
}

// ---------------------------------------------------------------------------
// Forward recursion.
// Cluster of 4 CTAs handles 4 batches. CTA rank r owns E columns
// [128r, 128r+128). Thread layout (matvec): cg = t&31 (float4 col group),
// gp = (t>>5)&1 (batch pair), seg = t>>6 (8 c-segments of 64).
// Thread layout (alpha): g = t>>7 (batch in group), col = t&127.
__global__ void __cluster_dims__(RANKS, 1, 1) __launch_bounds__(512, 1)
forward_kernel(const float* __restrict__ emit,
               const void*  __restrict__ mask,
               const float* __restrict__ tfs,
               const float* __restrict__ tte)
{
    __shared__ float p[2][CDIM][4];        // [parity][c][g]  (16 KB)
    __shared__ float part[8][4][COLS];     // [seg][g][col]   (16 KB)
    __shared__ float m_mail[2][RANKS][4];  // [parity][src rank][g]
    __shared__ float wred[4][4];           // [g][warp-within-g]
    __shared__ float wsum[4][4];
    __shared__ float fm_mail[RANKS][4], fs_mail[RANKS][4];

    const int t    = threadIdx.x;
    const int cta  = blockIdx.x;
    const int rank = cta & 3;
    const int bbase = (cta >> 2) << 2;

    // alpha-owner mapping
    const int g       = t >> 7;
    const int col     = t & 127;
    const int cg_glob = rank * COLS + col;     // this thread's global state index
    const int lane    = t & 31;
    const int w4      = (t >> 5) & 3;

    // matvec mapping
    const int cg  = t & 31;
    const int gp  = (t >> 5) & 1;
    const int seg = t >> 6;

    // precompute peer DSMEM base addresses
    unsigned p_peer[RANKS], m_peer[RANKS];
    {
        unsigned pb = smem_u32(&p[0][0][0]);
        unsigned mb = smem_u32(&m_mail[0][0][0]);
        #pragma unroll
        for (int r = 0; r < RANKS; r++) {
            p_peer[r] = mapa_rank(pb, r);
            m_peer[r] = mapa_rank(mb, r);
        }
    }
    unsigned fm0 = mapa_rank(smem_u32(&fm_mail[0][0]), 0);
    unsigned fs0 = mapa_rank(smem_u32(&fs_mail[0][0]), 0);

    // alpha_0 = emit[0,b,:] + trans_from_start
    float a = emit[(size_t)(bbase + g) * CDIM + cg_glob] + tfs[cg_glob];

    int par = 0;
    for (int i = 1; i < LDIM; i++) {
        int act = get_mask(mask, i * BDIM + bbase + g);
        if (!__syncthreads_or(act)) continue;   // uniform across whole cluster

        // ---- local per-batch max of alpha (this CTA's 128-col slice) ----
        float m = a;
        #pragma unroll
        for (int o = 16; o; o >>= 1) m = fmaxf(m, __shfl_xor_sync(0xffffffffu, m, o));
        if (lane == 0) wred[g][w4] = m;
        __syncthreads();
        float mloc = fmaxf(fmaxf(wred[g][0], wred[g][1]), fmaxf(wred[g][2], wred[g][3]));

        // ---- p slice (local-max shifted), broadcast to all 4 CTAs ----
        float pv = expf(a - mloc);
        unsigned off = (unsigned)(((par * CDIM + cg_glob) * 4 + g) * 4);
        #pragma unroll
        for (int r = 0; r < RANKS; r++) stc_f32(p_peer[r] + off, pv);
        if (t < 16) {
            int dr = t >> 2, dg = t & 3;
            float ml = fmaxf(fmaxf(wred[dg][0], wred[dg][1]), fmaxf(wred[dg][2], wred[dg][3]));
            stc_f32(m_peer[dr] + (unsigned)((par * RANKS * 4 + rank * 4 + dg) * 4), ml);
        }
        cluster_sync_();   // release stores; acquire peers' stores

        // ---- matvec on this CTA's E slice: all 4 batches per E load ----
        {
            const unsigned long long* Ep =
                (const unsigned long long*)(g_E + (size_t)(seg * 64) * CDIM + rank * COLS + cg * 4);
            const float2* pp = (const float2*)&p[par][seg * 64][gp * 2];
            unsigned long long a00 = 0, a01 = 0, a10 = 0, a11 = 0;
            #pragma unroll 8
            for (int c = 0; c < 64; c++) {
                unsigned long long e0 = Ep[(size_t)c * 256];      // cols 4cg,4cg+1
                unsigned long long e1 = Ep[(size_t)c * 256 + 1];  // cols 4cg+2,4cg+3
                float2 pv2 = pp[c * 2];
                unsigned long long pa = dup2(pv2.x);
                unsigned long long pb = dup2(pv2.y);
                a00 = ffma2(pa, e0, a00);
                a01 = ffma2(pa, e1, a01);
                a10 = ffma2(pb, e0, a10);
                a11 = ffma2(pb, e1, a11);
            }
            float x0, x1, x2, x3;
            unpack2(a00, x0, x1); unpack2(a01, x2, x3);
            *(float4*)&part[seg][gp * 2][cg * 4] = make_float4(x0, x1, x2, x3);
            unpack2(a10, x0, x1); unpack2(a11, x2, x3);
            *(float4*)&part[seg][gp * 2 + 1][cg * 4] = make_float4(x0, x1, x2, x3);
        }
        __syncthreads();

        // ---- combine rank partials with rescale, update alpha ----
        float m0 = m_mail[par][0][g], m1 = m_mail[par][1][g];
        float m2 = m_mail[par][2][g], m3 = m_mail[par][3][g];
        float mg = fmaxf(fmaxf(m0, m1), fmaxf(m2, m3));
        float s = expf(m0 - mg) * (part[0][g][col] + part[1][g][col])
                + expf(m1 - mg) * (part[2][g][col] + part[3][g][col])
                + expf(m2 - mg) * (part[4][g][col] + part[5][g][col])
                + expf(m3 - mg) * (part[6][g][col] + part[7][g][col]);
        float anew = mg + logf(s) + emit[((size_t)i * BDIM + bbase + g) * CDIM + cg_glob];
        a = act ? anew : a;
        par ^= 1;
    }

    // ---- log_z_b = logsumexp(alpha + trans_to_end), across 4 CTAs ----
    float v = a + tte[cg_glob];
    float m = v;
    #pragma unroll
    for (int o = 16; o; o >>= 1) m = fmaxf(m, __shfl_xor_sync(0xffffffffu, m, o));
    if (lane == 0) wred[g][w4] = m;
    __syncthreads();
    float mloc = fmaxf(fmaxf(wred[g][0], wred[g][1]), fmaxf(wred[g][2], wred[g][3]));
    float e = expf(v - mloc);
    #pragma unroll
    for (int o = 16; o; o >>= 1) e += __shfl_xor_sync(0xffffffffu, e, o);
    if (lane == 0) wsum[g][w4] = e;
    __syncthreads();
    if (t < 4) {
        int g2 = t;
        float ml = fmaxf(fmaxf(wred[g2][0], wred[g2][1]), fmaxf(wred[g2][2], wred[g2][3]));
        float sl = ((wsum[g2][0] + wsum[g2][1]) + (wsum[g2][2] + wsum[g2][3]));
        stc_f32(fm0 + (unsigned)((rank * 4 + g2) * 4), ml);
        stc_f32(fs0 + (unsigned)((rank * 4 + g2) * 4), sl);
    }
    cluster_sync_();
    if (rank == 0 && t < 4) {
        int g2 = t;
        float f0 = fm_mail[0][g2], f1 = fm_mail[1][g2], f2 = fm_mail[2][g2], f3 = fm_mail[3][g2];
        float mg = fmaxf(fmaxf(f0, f1), fmaxf(f2, f3));
        float tot = fs_mail[0][g2] * expf(f0 - mg) + fs_mail[1][g2] * expf(f1 - mg)
                  + fs_mail[2][g2] * expf(f2 - mg) + fs_mail[3][g2] * expf(f3 - mg);
        g_logz[bbase + g2] = mg + logf(tot);
    }
}

// ---------------------------------------------------------------------------
__global__ __launch_bounds__(512) void score_kernel(
    const float* __restrict__ emit,
    const int*   __restrict__ target,
    const void*  __restrict__ mask,
    const float* __restrict__ trans,
    const float* __restrict__ tfs,
    const float* __restrict__ tte)
{
    const int idx = blockIdx.x * 512 + threadIdx.x;
    const int i = idx >> 6;
    const int b = idx & 63;
    const int t = threadIdx.x, warp = t >> 5, lane = t & 31;

    float contrib = 0.f;
    if (get_mask(mask, i * BDIM + b)) {
        int ti = target[i * BDIM + b];
        contrib = emit[((size_t)i * BDIM + b) * CDIM + ti];
        if (i > 0) {
            int tp = target[(i - 1) * BDIM + b];
            contrib += trans[(size_t)tp * CDIM + ti];
        } else {
            contrib += tfs[ti];
        }
        int nxt = (i + 1 < LDIM) ? get_mask(mask, (i + 1) * BDIM + b) : 0;
        if (!nxt) contrib += tte[ti];
    }
    __shared__ float red[16];
    #pragma unroll
    for (int o = 16; o; o >>= 1) contrib += __shfl_xor_sync(0xffffffffu, contrib, o);
    if (lane == 0) red[warp] = contrib;
    __syncthreads();
    if (t == 0) {
        float s = 0.f;
        #pragma unroll
        for (int w = 0; w < 16; w++) s += red[w];
        g_scorep[blockIdx.x] = s;
    }
}

// ---------------------------------------------------------------------------
__global__ void finalize_kernel(float* __restrict__ out) {
    if (threadIdx.x == 0) {
        float lz = 0.f, sc = 0.f;
        for (int b = 0; b < BDIM; b++) { lz += g_logz[b]; sc += g_scorep[b]; }
        out[0] = (lz - sc) / (float)BDIM;
    }
}

// ---------------------------------------------------------------------------
extern "C" void kernel_launch(void* const* d_in, const int* in_sizes, int n_in,
                              void* d_out, int out_size) {
    const float* emit   = (const float*)d_in[0];
    const int*   target = (const int*)  d_in[1];
    const void*  mask   =               d_in[2];
    const float* trans  = (const float*)d_in[3];
    const float* tfs    = (const float*)d_in[4];
    const float* tte    = (const float*)d_in[5];
    float* out = (float*)d_out;

    probe_mask_kernel<<<1, 1>>>((const unsigned char*)mask);
    exp_trans_kernel<<<(CDIM * CDIM) / 512, 512>>>(trans);
    forward_kernel<<<BDIM, 512>>>(emit, mask, tfs, tte);
    score_kernel<<<64, 512>>>(emit, target, mask, trans, tfs, tte);
    finalize_kernel<<<1, 32>>>(out);
}

// round 3
// speedup vs baseline: 2.6272x; 1.6596x over previous
#include <cuda_runtime.h>
#include <math.h>
#include <stdint.h>

#define LDIM 512
#define BDIM 64
#define CDIM 512
#define RANKS 8
#define COLS 64           // E-columns per CTA (CDIM / RANKS)
#define GRPB 4            // batches per cluster

__device__ float g_logz[BDIM];
__device__ float g_scorep[BDIM];
__device__ int   g_mask_byte;

// ---------------------------------------------------------------------------
__device__ __forceinline__ unsigned smem_u32(const void* p) {
    return (unsigned)__cvta_generic_to_shared(p);
}
__device__ __forceinline__ unsigned mapa_rank(unsigned saddr, unsigned rank) {
    unsigned r;
    asm("mapa.shared::cluster.u32 %0, %1, %2;" : "=r"(r) : "r"(saddr), "r"(rank));
    return r;
}
__device__ __forceinline__ void stc_f32(unsigned saddr, float v) {
    asm volatile("st.shared::cluster.f32 [%0], %1;" :: "r"(saddr), "f"(v) : "memory");
}
__device__ __forceinline__ void stc_v4(unsigned saddr, float4 v) {
    asm volatile("st.shared::cluster.v4.f32 [%0], {%1,%2,%3,%4};"
                 :: "r"(saddr), "f"(v.x), "f"(v.y), "f"(v.z), "f"(v.w) : "memory");
}
__device__ __forceinline__ void cluster_sync_() {
    asm volatile("barrier.cluster.arrive.aligned;" ::: "memory");
    asm volatile("barrier.cluster.wait.aligned;"   ::: "memory");
}
__device__ __forceinline__ unsigned long long ffma2(unsigned long long a,
                                                    unsigned long long b,
                                                    unsigned long long c) {
    unsigned long long d;
    asm("fma.rn.f32x2 %0, %1, %2, %3;" : "=l"(d) : "l"(a), "l"(b), "l"(c));
    return d;
}
__device__ __forceinline__ unsigned long long dup2(float v) {
    unsigned long long r; unsigned u = __float_as_uint(v);
    asm("mov.b64 %0, {%1, %1};" : "=l"(r) : "r"(u));
    return r;
}
__device__ __forceinline__ float2 unpk(unsigned long long v) {
    unsigned a, b;
    asm("mov.b64 {%0, %1}, %2;" : "=r"(a), "=r"(b) : "l"(v));
    return make_float2(__uint_as_float(a), __uint_as_float(b));
}

// ---------------------------------------------------------------------------
__global__ void probe_mask_kernel(const unsigned char* __restrict__ m8) {
    int allnz = 1;
    for (int b = 0; b < BDIM; b++)
        if (m8[b] == 0) allnz = 0;
    g_mask_byte = allnz;
}
__device__ __forceinline__ int get_mask(const void* mask, int idx) {
    if (g_mask_byte) return ((const unsigned char*)mask)[idx] != 0;
    return ((const int*)mask)[idx] != 0;
}

// ---------------------------------------------------------------------------
struct __align__(16) SM {
    float E[CDIM * COLS];           // 128 KB  E[row][64] local-col slice
    float p[2][CDIM][GRPB];         // 16 KB   assembled p, double-buffered
    float part[32][GRPB][COLS];     // 32 KB   matvec partials per 16-row seg
    float stage[COLS][GRPB];        // 1 KB
    float m_mail[2][RANKS][GRPB];   // 256 B   local maxes from each rank
    float wred[8];
    float wsum[8];
    float fm[RANKS][GRPB], fs[RANKS][GRPB];
    unsigned char act4[LDIM][GRPB];
    unsigned char any[LDIM];
};

__global__ void __cluster_dims__(RANKS, 1, 1) __launch_bounds__(512, 1)
forward_kernel(const float* __restrict__ emit,
               const void*  __restrict__ mask,
               const float* __restrict__ trans,
               const float* __restrict__ tfs,
               const float* __restrict__ tte)
{
    extern __shared__ char smraw[];
    SM* sm = (SM*)smraw;

    const int t     = threadIdx.x;
    const int cta   = blockIdx.x;
    const int rank  = cta & (RANKS - 1);
    const int bbase = (cta >> 3) << 2;         // 4 batches per cluster

    // alpha-owner mapping (t < 256): g = batch-in-group, col = local column
    const int g   = (t >> 6) & 3;
    const int col = t & 63;
    const int cg_glob = rank * COLS + col;
    const int lane = t & 31;
    const int wrp  = t >> 5;

    // matvec mapping: cg = float4 col group (16), seg = 16-row segment (32)
    const int cg  = t & 15;
    const int seg = t >> 4;

    // peer DSMEM addresses
    unsigned p_peer[RANKS], m_peer[RANKS];
    {
        unsigned pb = smem_u32(&sm->p[0][0][0]);
        unsigned mb = smem_u32(&sm->m_mail[0][0][0]);
        #pragma unroll
        for (int r = 0; r < RANKS; r++) {
            p_peer[r] = mapa_rank(pb, r);
            m_peer[r] = mapa_rank(mb, r);
        }
    }
    unsigned fm0 = mapa_rank(smem_u32(&sm->fm[0][0]), 0);
    unsigned fs0 = mapa_rank(smem_u32(&sm->fs[0][0]), 0);

    // ---- init: E slice = exp(trans[:, rank*64 : rank*64+64]) ----
    for (int idx = t; idx < CDIM * COLS; idx += 512) {
        int row = idx >> 6, c = idx & 63;
        sm->E[idx] = expf(trans[(size_t)row * CDIM + rank * COLS + c]);
    }
    // ---- init: mask flags ----
    for (int i = t; i < LDIM; i += 512) {
        int anyv = 0;
        #pragma unroll
        for (int gg = 0; gg < GRPB; gg++) {
            int m = get_mask(mask, i * BDIM + bbase + gg);
            sm->act4[i][gg] = (unsigned char)m;
            anyv |= m;
        }
        sm->any[i] = (unsigned char)anyv;
    }
    // ---- init: alpha_0 ----
    float a = 0.f;
    if (t < 256)
        a = emit[(size_t)(bbase + g) * CDIM + cg_glob] + tfs[cg_glob];

    __syncthreads();
    cluster_sync_();

    int par = 0;
    for (int i = 1; i < LDIM; i++) {
        if (!sm->any[i]) continue;

        // ---- phase 1: per-batch local max over this rank's 64 cols ----
        if (t < 256) {
            float m = a;
            #pragma unroll
            for (int o = 16; o; o >>= 1) m = fmaxf(m, __shfl_xor_sync(0xffffffffu, m, o));
            if (lane == 0) sm->wred[wrp] = m;
        }
        __syncthreads();

        // ---- phase 2: p-slice + emit prefetch ----
        float e_reg = 0.f, mloc = 0.f;
        if (t < 256) {
            mloc = fmaxf(sm->wred[2 * g], sm->wred[2 * g + 1]);
            sm->stage[col][g] = __expf(a - mloc);
            e_reg = emit[((size_t)i * BDIM + bbase + g) * CDIM + cg_glob];
        }
        __syncthreads();

        // ---- phase 3: push p + local max to all 8 ranks ----
        if (t < 64) {
            float4 pv4 = *(const float4*)&sm->stage[t][0];
            unsigned off = (unsigned)(((par * CDIM + rank * COLS + t) * GRPB) * 4);
            #pragma unroll
            for (int rr = 0; rr < RANKS; rr++) {
                int r = (rank + rr) & (RANKS - 1);
                stc_v4(p_peer[r] + off, pv4);
            }
        }
        if (t < 32) {
            int dr = t >> 2, dg = t & 3;
            float ml = fmaxf(sm->wred[2 * dg], sm->wred[2 * dg + 1]);
            stc_f32(m_peer[dr] + (unsigned)(((par * RANKS + rank) * GRPB + dg) * 4), ml);
        }
        cluster_sync_();

        // ---- phase 4: matvec on SMEM E slice, 4 batches per E element ----
        {
            const ulonglong2* Ev = (const ulonglong2*)sm->E + (size_t)seg * 16 * (COLS / 4) + cg;
            const float4*     pv = (const float4*)&sm->p[par][seg * 16][0];
            unsigned long long ac[8];
            #pragma unroll
            for (int k = 0; k < 8; k++) ac[k] = 0ull;
            #pragma unroll
            for (int c = 0; c < 16; c++) {
                ulonglong2 e  = Ev[(size_t)c * (COLS / 4)];
                float4     pq = pv[c];
                unsigned long long d0 = dup2(pq.x), d1 = dup2(pq.y),
                                   d2 = dup2(pq.z), d3 = dup2(pq.w);
                ac[0] = ffma2(d0, e.x, ac[0]); ac[1] = ffma2(d0, e.y, ac[1]);
                ac[2] = ffma2(d1, e.x, ac[2]); ac[3] = ffma2(d1, e.y, ac[3]);
                ac[4] = ffma2(d2, e.x, ac[4]); ac[5] = ffma2(d2, e.y, ac[5]);
                ac[6] = ffma2(d3, e.x, ac[6]); ac[7] = ffma2(d3, e.y, ac[7]);
            }
            #pragma unroll
            for (int gg = 0; gg < GRPB; gg++) {
                float2 lo = unpk(ac[2 * gg]), hi = unpk(ac[2 * gg + 1]);
                *(float4*)&sm->part[seg][gg][cg * 4] = make_float4(lo.x, lo.y, hi.x, hi.y);
            }
        }
        __syncthreads();

        // ---- phase 5: combine 32 segments with per-rank rescale ----
        if (t < 256) {
            float mg = sm->m_mail[par][0][g];
            #pragma unroll
            for (int r = 1; r < RANKS; r++) mg = fmaxf(mg, sm->m_mail[par][r][g]);
            float s = 0.f;
            #pragma unroll
            for (int r = 0; r < RANKS; r++) {
                float ps = (sm->part[4 * r][g][col]     + sm->part[4 * r + 1][g][col])
                         + (sm->part[4 * r + 2][g][col] + sm->part[4 * r + 3][g][col]);
                s += __expf(sm->m_mail[par][r][g] - mg) * ps;
            }
            float anew = mg + __logf(s) + e_reg;
            if (sm->act4[i][g]) a = anew;
        }
        par ^= 1;
    }

    // ---- final: log_z = logsumexp(alpha + tte) across 8 ranks ----
    float v = -3.4e38f;
    if (t < 256) v = a + tte[cg_glob];
    {
        float m = v;
        #pragma unroll
        for (int o = 16; o; o >>= 1) m = fmaxf(m, __shfl_xor_sync(0xffffffffu, m, o));
        if (t < 256 && lane == 0) sm->wred[wrp] = m;
    }
    __syncthreads();
    float mloc = 0.f, e = 0.f;
    if (t < 256) {
        mloc = fmaxf(sm->wred[2 * g], sm->wred[2 * g + 1]);
        e = expf(v - mloc);
        #pragma unroll
        for (int o = 16; o; o >>= 1) e += __shfl_xor_sync(0xffffffffu, e, o);
        if (lane == 0) sm->wsum[wrp] = e;
    }
    __syncthreads();
    if (t < 4) {
        float ml = fmaxf(sm->wred[2 * t], sm->wred[2 * t + 1]);
        float sl = sm->wsum[2 * t] + sm->wsum[2 * t + 1];
        stc_f32(fm0 + (unsigned)((rank * GRPB + t) * 4), ml);
        stc_f32(fs0 + (unsigned)((rank * GRPB + t) * 4), sl);
    }
    cluster_sync_();
    if (rank == 0 && t < 4) {
        float mg = sm->fm[0][t];
        #pragma unroll
        for (int r = 1; r < RANKS; r++) mg = fmaxf(mg, sm->fm[r][t]);
        float tot = 0.f;
        #pragma unroll
        for (int r = 0; r < RANKS; r++) tot += sm->fs[r][t] * expf(sm->fm[r][t] - mg);
        g_logz[bbase + t] = mg + logf(tot);
    }
}

// ---------------------------------------------------------------------------
__global__ __launch_bounds__(512) void score_kernel(
    const float* __restrict__ emit,
    const int*   __restrict__ target,
    const void*  __restrict__ mask,
    const float* __restrict__ trans,
    const float* __restrict__ tfs,
    const float* __restrict__ tte)
{
    const int idx = blockIdx.x * 512 + threadIdx.x;
    const int i = idx >> 6;
    const int b = idx & 63;
    const int t = threadIdx.x, warp = t >> 5, lane = t & 31;

    float contrib = 0.f;
    if (get_mask(mask, i * BDIM + b)) {
        int ti = target[i * BDIM + b];
        contrib = emit[((size_t)i * BDIM + b) * CDIM + ti];
        if (i > 0) {
            int tp = target[(i - 1) * BDIM + b];
            contrib += trans[(size_t)tp * CDIM + ti];
        } else {
            contrib += tfs[ti];
        }
        int nxt = (i + 1 < LDIM) ? get_mask(mask, (i + 1) * BDIM + b) : 0;
        if (!nxt) contrib += tte[ti];
    }
    __shared__ float red[16];
    #pragma unroll
    for (int o = 16; o; o >>= 1) contrib += __shfl_xor_sync(0xffffffffu, contrib, o);
    if (lane == 0) red[warp] = contrib;
    __syncthreads();
    if (t == 0) {
        float s = 0.f;
        #pragma unroll
        for (int w = 0; w < 16; w++) s += red[w];
        g_scorep[blockIdx.x] = s;
    }
}

// ---------------------------------------------------------------------------
__global__ void finalize_kernel(float* __restrict__ out) {
    if (threadIdx.x == 0) {
        float lz = 0.f, sc = 0.f;
        for (int b = 0; b < BDIM; b++) { lz += g_logz[b]; sc += g_scorep[b]; }
        out[0] = (lz - sc) / (float)BDIM;
    }
}

// ---------------------------------------------------------------------------
extern "C" void kernel_launch(void* const* d_in, const int* in_sizes, int n_in,
                              void* d_out, int out_size) {
    const float* emit   = (const float*)d_in[0];
    const int*   target = (const int*)  d_in[1];
    const void*  mask   =               d_in[2];
    const float* trans  = (const float*)d_in[3];
    const float* tfs    = (const float*)d_in[4];
    const float* tte    = (const float*)d_in[5];
    float* out = (float*)d_out;

    cudaFuncSetAttribute(forward_kernel,
                         cudaFuncAttributeMaxDynamicSharedMemorySize, (int)sizeof(SM));

    probe_mask_kernel<<<1, 1>>>((const unsigned char*)mask);
    forward_kernel<<<16 * RANKS, 512, sizeof(SM)>>>(emit, mask, trans, tfs, tte);
    score_kernel<<<64, 512>>>(emit, target, mask, trans, tfs, tte);
    finalize_kernel<<<1, 32>>>(out);
}